// round 15
// baseline (speedup 1.0000x reference)
#include <cuda_runtime.h>
#include <cuda_fp16.h>
#include <cstdint>

typedef unsigned int u32;
typedef unsigned long long u64;

#define NQ   4096
#define NR   4096
#define NV   128
#define ND   128
#define KTOP 16
#define CAND 96
#define RCAP 768
#define CQ   16

// ---------------- device globals ----------------
__device__ u32 g_Tfp8[(size_t)NR * NV * ND / 4];   // 64 MB e4m3, fragment order
__device__ u32 g_Qfp8[(size_t)NQ * ND / 4];        // 512 KB, fragment order
__device__ u32 g_rowmax[(size_t)NQ * NR];          // okey(u32); RED.MAX target
__device__ int g_rowcnt[NR];
__device__ u32 g_rowlist[(size_t)NR * RCAP];       // (q<<7)|slot
__device__ int g_cand_row[(size_t)NQ * CAND];
__device__ u64 g_cand_key[(size_t)NQ * CAND];      // (okey(score)<<32)|(127-v)
__device__ int g_cand_cnt[NQ];

// ---------------- helpers ----------------
__device__ __forceinline__ u32 okey(float f) {
    u32 b = __float_as_uint(f);
    return (b & 0x80000000u) ? ~b : (b | 0x80000000u);
}
__device__ __forceinline__ float unokey(u32 u) {
    u32 b = (u & 0x80000000u) ? (u & 0x7fffffffu) : ~u;
    return __uint_as_float(b);
}
__device__ __forceinline__ float fmas(float a, float b, float c) {
    float d; asm("fma.rn.f32 %0, %1, %2, %3;" : "=f"(d) : "f"(a), "f"(b), "f"(c));
    return d;
}
__device__ __forceinline__ u32 pack_e4m3x4(float4 a) {
    unsigned short h0, h1; u32 r;
    asm("cvt.rn.satfinite.e4m3x2.f32 %0, %1, %2;" : "=h"(h0) : "f"(a.y), "f"(a.x));
    asm("cvt.rn.satfinite.e4m3x2.f32 %0, %1, %2;" : "=h"(h1) : "f"(a.w), "f"(a.z));
    asm("mov.b32 %0, {%1, %2};" : "=r"(r) : "h"(h0), "h"(h1));
    return r;
}
__device__ __forceinline__ u32 smem_u32(const void* p) {
    u32 a; asm("{ .reg .u64 t; cvta.to.shared.u64 t, %1; cvt.u32.u64 %0, t; }"
               : "=r"(a) : "l"(p));
    return a;
}
__device__ __forceinline__ void cpasync16(u32 saddr, const void* g) {
    asm volatile("cp.async.cg.shared.global [%0], [%1], 16;"
                 :: "r"(saddr), "l"(g) : "memory");
}
__device__ __forceinline__ u32 hmax2(u32 a, u32 b) {
    u32 d; asm("max.f16x2 %0, %1, %2;" : "=r"(d) : "r"(a), "r"(b)); return d;
}
__device__ __forceinline__ float hmax_to_f(u32 p) {
    __half2 h = *reinterpret_cast<__half2*>(&p);
    float2 f = __half22float2(h);
    return fmaxf(f.x, f.y);
}
#define CP_COMMIT() asm volatile("cp.async.commit_group;" ::: "memory")
#define CP_WAIT(n)  asm volatile("cp.async.wait_group %0;" :: "n"(n) : "memory")
#define BAR_GRP(id) asm volatile("bar.sync %0, 128;" :: "r"(id) : "memory")

// fp8 x fp8 -> fp16 accumulate (2x rate vs f32 acc); c = 2 x f16x2 regs
#define MMAFP8H(c, A, B0, B1) \
    asm volatile("mma.sync.aligned.m16n8k32.row.col.f16.e4m3.e4m3.f16 " \
        "{%0,%1}, {%2,%3,%4,%5}, {%6,%7}, {%0,%1};" \
        : "+r"((c)[0]), "+r"((c)[1]) \
        : "r"((A)[0]), "r"((A)[1]), "r"((A)[2]), "r"((A)[3]), "r"(B0), "r"(B1))

#define MMAFP8H_INIT(c, A, B0, B1) \
    asm volatile("mma.sync.aligned.m16n8k32.row.col.f16.e4m3.e4m3.f16 " \
        "{%0,%1}, {%2,%3,%4,%5}, {%6,%7}, {%8,%8};" \
        : "=r"((c)[0]), "=r"((c)[1]) \
        : "r"((A)[0]), "r"((A)[1]), "r"((A)[2]), "r"((A)[3]), "r"(B0), "r"(B1), \
          "r"(0u))

// ---------------- conversion (fragment-order layout) + fused init ----------
__global__ void conv_T_kernel(const float* __restrict__ T) {
    int t = blockIdx.x * 256 + threadIdx.x;
    if (t < NR) g_rowcnt[t] = 0;
    if (t < NQ * CAND) g_cand_key[t] = 0ull;
    int tg = t & 3, v = (t >> 2) & 127, r = t >> 9;
    const float* src = T + (size_t)r * 16384 + v * 128;
    u32 out[8];
    #pragma unroll
    for (int ks = 0; ks < 4; ks++)
        #pragma unroll
        for (int h = 0; h < 2; h++) {
            float4 f = *(const float4*)(src + ks * 32 + h * 16 + tg * 4);
            out[ks * 2 + h] = pack_e4m3x4(f);
        }
    uint4* dst = (uint4*)g_Tfp8 + (size_t)r * 1024 + v * 8 + tg * 2;
    dst[0] = make_uint4(out[0], out[1], out[2], out[3]);
    dst[1] = make_uint4(out[4], out[5], out[6], out[7]);
}
__global__ void conv_Q_kernel(const float* __restrict__ Q) {
    int t = blockIdx.x * 256 + threadIdx.x;
    int tg = t & 3, q = t >> 2;
    const float* src = Q + (size_t)q * 128;
    u32 out[8];
    #pragma unroll
    for (int ks = 0; ks < 4; ks++)
        #pragma unroll
        for (int h = 0; h < 2; h++) {
            float4 f = *(const float4*)(src + ks * 32 + h * 16 + tg * 4);
            out[ks * 2 + h] = pack_e4m3x4(f);
        }
    uint4* dst = (uint4*)g_Qfp8 + (size_t)q * 8 + tg * 2;
    dst[0] = make_uint4(out[0], out[1], out[2], out[3]);
    dst[1] = make_uint4(out[4], out[5], out[6], out[7]);
}

// ============================================================================
// Phase A: fp8 mma.sync (fp16 acc), 4-warp-group decoupled, ROW PAIRS per
// barrier. Each group owns a 6-stage (3-pair-slot) 24KB cp.async ring in
// dynamic smem (96KB total); one bar.sync + one CP_WAIT per 2 rows.
// In-pair order: B0 loads, MMA0, B1 loads, epi0, MMA1, epi1 — row-0's shfl/
// RED chains overlap row-1's independent MMA stream.
// ============================================================================
__global__ void __launch_bounds__(512, 1)
score_mma_kernel() {
    extern __shared__ __align__(128) u32 dynpool[];   // 96 KB

    const int tid  = threadIdx.x;
    const int lane = tid & 31;
    const int wid  = tid >> 5;
    const int wm   = wid & 3;      // 32q slice; SMSP id
    const int wn   = wid >> 2;     // 32v quarter / group id
    const int g    = lane >> 2;
    const int tg   = lane & 3;
    const int qt   = blockIdx.x;   // 0..31 (fast -> L2 row sharing)
    const int rg   = blockIdx.y;   // 0..127

    u32* gbase = dynpool + wn * 6144;          // 6 stages x 1024 u32
    const u32 gbaddr = smem_u32(gbase);

    // ---- prologue: stage Q tile (16KB) into dynpool[0..4095], swizzled ----
    {
        const uint4* qsrc = (const uint4*)g_Qfp8 + (size_t)(qt * 128) * 8;
        #pragma unroll
        for (int i = 0; i < 2; i++) {
            int e = i * 512 + tid;
            int q = e >> 3, p = e & 7;
            *(uint4*)(dynpool + q * 32 + ((p ^ (q & 7)) << 2)) = qsrc[e];
        }
    }
    __syncthreads();

    // ---- hoist A fragments (full K, 2 q-tiles of 16) from swizzled Q ----
    u32 A[4][2][4];
    #pragma unroll
    for (int ks = 0; ks < 4; ks++)
        #pragma unroll
        for (int mt = 0; mt < 2; mt++) {
            int qlo = wm * 32 + mt * 16 + g;
            int j = tg * 8 + ks * 2;
            int c = j >> 2, w = j & 3;
            const u32* p0 = dynpool + qlo * 32 + ((c ^ g) << 2) + w;
            uint2 a02 = *(const uint2*)p0;
            uint2 a13 = *(const uint2*)(p0 + 256);
            A[ks][mt][0] = a02.x; A[ks][mt][2] = a02.y;
            A[ks][mt][1] = a13.x; A[ks][mt][3] = a13.y;
        }
    __syncthreads();   // all hoists done before cp.async overwrites pool

    // ---- staging map: group's 128 threads stage a 4KB quarter per row ----
    const int u = wm * 32 + lane;
    u32 soff[2];
    #pragma unroll
    for (int j4 = 0; j4 < 2; j4++) {
        int ck = j4 * 128 + u;
        int vl = ck >> 3, p = ck & 7;
        soff[j4] = (u32)(vl * 128 + ((p ^ (vl & 7)) * 16));
    }
    const uint4* tq = (const uint4*)g_Tfp8 + (size_t)(rg * 32) * 1024 + wn * 256;

    // prologue: stage pairs 0 (rows 0,1 -> stages 0,1) and 1 (rows 2,3 -> 2,3)
    #pragma unroll
    for (int pr = 0; pr < 2; pr++) {
        #pragma unroll
        for (int rr = 0; rr < 2; rr++) {
            int row = pr * 2 + rr;
            const uint4* gsrc = tq + (size_t)row * 1024;
            u32 dst = gbaddr + (u32)row * 4096u;
            #pragma unroll
            for (int j4 = 0; j4 < 2; j4++)
                cpasync16(dst + soff[j4], gsrc + j4 * 128 + u);
        }
        CP_COMMIT();
    }
    CP_WAIT(1);   // pair 0 complete (own copies); group bar publishes

    u32 boff0[4], boff1[4];
    #pragma unroll
    for (int nt = 0; nt < 4; nt++) {
        int vl = nt * 8 + g;
        boff0[nt] = (u32)(vl * 32 + (((2 * tg) ^ g) << 2));
        boff1[nt] = (u32)(vl * 32 + (((2 * tg + 1) ^ g) << 2));
    }

    u32* rmbase = g_rowmax + (size_t)(qt * 128 + wm * 32 + g) * NR + rg * 32;
    const int barid = wn + 1;

    #pragma unroll 1
    for (int pi = 0; pi < 16; pi++) {
        BAR_GRP(barid);   // group: pair pi-1 reads done; pair pi published

        if (pi + 2 < 16) {   // stage pair pi+2 into slot (pi+2)%3
            int ps = (pi + 2) % 3;
            #pragma unroll
            for (int rr = 0; rr < 2; rr++) {
                const uint4* gsrc = tq + (size_t)(2 * (pi + 2) + rr) * 1024;
                u32 dst = gbaddr + (u32)(ps * 2 + rr) * 4096u;
                #pragma unroll
                for (int j4 = 0; j4 < 2; j4++)
                    cpasync16(dst + soff[j4], gsrc + j4 * 128 + u);
            }
            CP_COMMIT();
        }

        const u32* buf0 = gbase + (pi % 3) * 2048;
        const u32* buf1 = buf0 + 1024;

        // ---- row 0 of pair: B loads + MMAs ----
        u32 B[4][8];
        #pragma unroll
        for (int nt = 0; nt < 4; nt++) {
            uint4 b0 = *(const uint4*)(buf0 + boff0[nt]);
            uint4 b1 = *(const uint4*)(buf0 + boff1[nt]);
            B[nt][0] = b0.x; B[nt][1] = b0.y; B[nt][2] = b0.z; B[nt][3] = b0.w;
            B[nt][4] = b1.x; B[nt][5] = b1.y; B[nt][6] = b1.z; B[nt][7] = b1.w;
        }
        u32 acc0[2][4][2];
        #pragma unroll
        for (int mt = 0; mt < 2; mt++)
            #pragma unroll
            for (int nt = 0; nt < 4; nt++)
                MMAFP8H_INIT(acc0[mt][nt], A[0][mt], B[nt][0], B[nt][1]);
        #pragma unroll
        for (int ks = 1; ks < 4; ks++)
            #pragma unroll
            for (int mt = 0; mt < 2; mt++)
                #pragma unroll
                for (int nt = 0; nt < 4; nt++)
                    MMAFP8H(acc0[mt][nt], A[ks][mt], B[nt][ks * 2], B[nt][ks * 2 + 1]);

        // ---- row 1 B loads (independent of epi0) ----
        u32 C[4][8];
        #pragma unroll
        for (int nt = 0; nt < 4; nt++) {
            uint4 b0 = *(const uint4*)(buf1 + boff0[nt]);
            uint4 b1 = *(const uint4*)(buf1 + boff1[nt]);
            C[nt][0] = b0.x; C[nt][1] = b0.y; C[nt][2] = b0.z; C[nt][3] = b0.w;
            C[nt][4] = b1.x; C[nt][5] = b1.y; C[nt][6] = b1.z; C[nt][7] = b1.w;
        }

        // ---- epilogue row 0 (shfl/RED chains overlap row-1 MMAs) ----
        #pragma unroll
        for (int mt = 0; mt < 2; mt++) {
            u32 e0 = hmax2(hmax2(acc0[mt][0][0], acc0[mt][1][0]),
                           hmax2(acc0[mt][2][0], acc0[mt][3][0]));
            u32 e1 = hmax2(hmax2(acc0[mt][0][1], acc0[mt][1][1]),
                           hmax2(acc0[mt][2][1], acc0[mt][3][1]));
            e0 = hmax2(e0, __shfl_xor_sync(0xffffffffu, e0, 1));
            e0 = hmax2(e0, __shfl_xor_sync(0xffffffffu, e0, 2));
            e1 = hmax2(e1, __shfl_xor_sync(0xffffffffu, e1, 1));
            e1 = hmax2(e1, __shfl_xor_sync(0xffffffffu, e1, 2));
            if (tg == 0) {
                atomicMax(rmbase + (size_t)(mt * 16) * NR + 2 * pi, okey(hmax_to_f(e0)));
                atomicMax(rmbase + (size_t)(mt * 16 + 8) * NR + 2 * pi, okey(hmax_to_f(e1)));
            }
        }

        // ---- row 1 MMAs ----
        u32 acc1[2][4][2];
        #pragma unroll
        for (int mt = 0; mt < 2; mt++)
            #pragma unroll
            for (int nt = 0; nt < 4; nt++)
                MMAFP8H_INIT(acc1[mt][nt], A[0][mt], C[nt][0], C[nt][1]);
        #pragma unroll
        for (int ks = 1; ks < 4; ks++)
            #pragma unroll
            for (int mt = 0; mt < 2; mt++)
                #pragma unroll
                for (int nt = 0; nt < 4; nt++)
                    MMAFP8H(acc1[mt][nt], A[ks][mt], C[nt][ks * 2], C[nt][ks * 2 + 1]);

        // ---- epilogue row 1 ----
        #pragma unroll
        for (int mt = 0; mt < 2; mt++) {
            u32 e0 = hmax2(hmax2(acc1[mt][0][0], acc1[mt][1][0]),
                           hmax2(acc1[mt][2][0], acc1[mt][3][0]));
            u32 e1 = hmax2(hmax2(acc1[mt][0][1], acc1[mt][1][1]),
                           hmax2(acc1[mt][2][1], acc1[mt][3][1]));
            e0 = hmax2(e0, __shfl_xor_sync(0xffffffffu, e0, 1));
            e0 = hmax2(e0, __shfl_xor_sync(0xffffffffu, e0, 2));
            e1 = hmax2(e1, __shfl_xor_sync(0xffffffffu, e1, 1));
            e1 = hmax2(e1, __shfl_xor_sync(0xffffffffu, e1, 2));
            if (tg == 0) {
                atomicMax(rmbase + (size_t)(mt * 16) * NR + 2 * pi + 1, okey(hmax_to_f(e0)));
                atomicMax(rmbase + (size_t)(mt * 16 + 8) * NR + 2 * pi + 1, okey(hmax_to_f(e1)));
            }
        }

        CP_WAIT(1);   // pair pi+1 complete (own); next bar publishes group-wide
    }
}

// ============================================================================
// Phase B: per-query candidate selection (rank-40 threshold, cap 96).
// ============================================================================
__global__ void select_kernel() {
    __shared__ u32 hist[256];
    __shared__ u32 s_b1, s_need, s_thr, s_cnt;
    const int tid = threadIdx.x;
    const int q = blockIdx.x;
    const uint4* sc4 = (const uint4*)(g_rowmax + (size_t)q * NR);

    hist[tid] = 0;
    __syncthreads();
    for (int j = tid; j < NR / 4; j += 256) {
        uint4 v = sc4[j];
        atomicAdd(&hist[v.x >> 24], 1u);
        atomicAdd(&hist[v.y >> 24], 1u);
        atomicAdd(&hist[v.z >> 24], 1u);
        atomicAdd(&hist[v.w >> 24], 1u);
    }
    __syncthreads();
    if (tid == 0) {
        u32 cum = 0;
        for (int b = 255; b >= 0; b--) {
            if (cum + hist[b] >= 40u) { s_b1 = (u32)b; s_need = 40u - cum; break; }
            cum += hist[b];
        }
    }
    __syncthreads();
    u32 b1 = s_b1, need = s_need;
    hist[tid] = 0;
    __syncthreads();
    for (int j = tid; j < NR / 4; j += 256) {
        uint4 v = sc4[j];
        if ((v.x >> 24) == b1) atomicAdd(&hist[(v.x >> 16) & 255u], 1u);
        if ((v.y >> 24) == b1) atomicAdd(&hist[(v.y >> 16) & 255u], 1u);
        if ((v.z >> 24) == b1) atomicAdd(&hist[(v.z >> 16) & 255u], 1u);
        if ((v.w >> 24) == b1) atomicAdd(&hist[(v.w >> 16) & 255u], 1u);
    }
    __syncthreads();
    if (tid == 0) {
        u32 cum = 0; u32 b2 = 0;
        for (int b = 255; b >= 0; b--) { cum += hist[b]; if (cum >= need) { b2 = (u32)b; break; } }
        s_thr = (b1 << 8) | b2;
        s_cnt = 0;
    }
    __syncthreads();
    u32 thr = s_thr;
    for (int j = tid; j < NR / 4; j += 256) {
        uint4 v = sc4[j];
        u32 e[4] = {v.x, v.y, v.z, v.w};
        #pragma unroll
        for (int c = 0; c < 4; c++) {
            if ((e[c] >> 16) >= thr) {
                int jj = j * 4 + c;
                u32 pos = atomicAdd(&s_cnt, 1u);
                if (pos < CAND) {
                    g_cand_row[(size_t)q * CAND + pos] = jj;
                    int p2 = atomicAdd(&g_rowcnt[jj], 1);
                    if (p2 < RCAP) g_rowlist[(size_t)jj * RCAP + p2] = ((u32)q << 7) | pos;
                }
            }
        }
    }
    __syncthreads();
    if (tid == 0) g_cand_cnt[q] = (int)(s_cnt < CAND ? s_cnt : CAND);
}

// ============================================================================
// Phase C: exact recompute, bitwise-matching reference (in-order fp32 FMA
// chain over k=0..127, single accumulator). CTA per row.
// ============================================================================
__global__ void __launch_bounds__(256)
exact_kernel(const float* __restrict__ Q, const float* __restrict__ T) {
    __shared__ __align__(16) float Ts[64 * 132];
    __shared__ __align__(16) float Qs[CQ * 128];
    __shared__ u64 sres[CQ];
    __shared__ u32 sent[CQ];

    const int tid = threadIdx.x;
    const int r = blockIdx.x;
    int nq = g_rowcnt[r];
    if (nq > RCAP) nq = RCAP;
    if (nq == 0) return;
    const int g = tid >> 6;
    const int v = tid & 63;

    #pragma unroll 1
    for (int h = 0; h < 2; h++) {
        __syncthreads();
        {
            const float4* src = (const float4*)(T + (size_t)r * NV * ND
                                                + (size_t)h * 64 * ND);
            #pragma unroll
            for (int i = 0; i < 8; i++) {
                int e = i * 256 + tid;
                int vv = e >> 5, k4 = e & 31;
                *(float4*)(Ts + vv * 132 + k4 * 4) = src[e];
            }
        }
        #pragma unroll 1
        for (int s = 0; s < nq; s += CQ) {
            int cnt = nq - s; if (cnt > CQ) cnt = CQ;
            __syncthreads();
            if (tid < CQ) {
                sres[tid] = 0ull;
                sent[tid] = (tid < cnt) ? g_rowlist[(size_t)r * RCAP + s + tid] : 0u;
            }
            __syncthreads();
            #pragma unroll
            for (int i = 0; i < 2; i++) {
                int e = i * 256 + tid;
                int qq = e >> 5, k4 = e & 31;
                if (qq < cnt) {
                    int qidx = (int)(sent[qq] >> 7);
                    *(float4*)(Qs + qq * 128 + k4 * 4) =
                        ((const float4*)(Q + (size_t)qidx * ND))[k4];
                }
            }
            __syncthreads();

            float a0 = 0.f, a1 = 0.f, a2 = 0.f, a3 = 0.f;
            const float* tv = Ts + v * 132;
            const float* q0 = Qs + (g * 4 + 0) * 128;
            const float* q1 = Qs + (g * 4 + 1) * 128;
            const float* q2 = Qs + (g * 4 + 2) * 128;
            const float* q3 = Qs + (g * 4 + 3) * 128;
            #pragma unroll 8
            for (int k = 0; k < 128; k += 4) {
                float4 t4 = *(const float4*)(tv + k);
                float4 x0 = *(const float4*)(q0 + k);
                float4 x1 = *(const float4*)(q1 + k);
                float4 x2 = *(const float4*)(q2 + k);
                float4 x3 = *(const float4*)(q3 + k);
                a0 = fmas(x0.x, t4.x, a0); a0 = fmas(x0.y, t4.y, a0);
                a0 = fmas(x0.z, t4.z, a0); a0 = fmas(x0.w, t4.w, a0);
                a1 = fmas(x1.x, t4.x, a1); a1 = fmas(x1.y, t4.y, a1);
                a1 = fmas(x1.z, t4.z, a1); a1 = fmas(x1.w, t4.w, a1);
                a2 = fmas(x2.x, t4.x, a2); a2 = fmas(x2.y, t4.y, a2);
                a2 = fmas(x2.z, t4.z, a2); a2 = fmas(x2.w, t4.w, a2);
                a3 = fmas(x3.x, t4.x, a3); a3 = fmas(x3.y, t4.y, a3);
                a3 = fmas(x3.z, t4.z, a3); a3 = fmas(x3.w, t4.w, a3);
            }
            u64 vb = (u64)(u32)(127 - (h * 64 + v));
            atomicMax(&sres[g * 4 + 0], ((u64)okey(a0) << 32) | vb);
            atomicMax(&sres[g * 4 + 1], ((u64)okey(a1) << 32) | vb);
            atomicMax(&sres[g * 4 + 2], ((u64)okey(a2) << 32) | vb);
            atomicMax(&sres[g * 4 + 3], ((u64)okey(a3) << 32) | vb);
            __syncthreads();
            if (tid < cnt) {
                u32 ent = sent[tid];
                int q = (int)(ent >> 7), slot = (int)(ent & 127u);
                atomicMax(&g_cand_key[(size_t)q * CAND + slot], sres[tid]);
            }
        }
    }
}

// ============================================================================
// Phase D: exact top-16 among <=96 candidates + gather (score desc, row desc).
// Output: [values 4096*16*128 | scores 4096*16 | ids 4096*16] (f32).
// ============================================================================
__global__ void final_kernel(const float* __restrict__ T, float* __restrict__ out) {
    int gw = (blockIdx.x * blockDim.x + threadIdx.x) >> 5;
    int lane = threadIdx.x & 31;
    if (gw >= NQ) return;
    const int q = gw;
    int cnt = g_cand_cnt[q];

    u64 key[3]; int argv[3];
    #pragma unroll
    for (int s = 0; s < 3; s++) {
        int idx = lane + 32 * s;
        key[s] = 0; argv[s] = 0;
        if (idx < cnt) {
            u64 ck = g_cand_key[(size_t)q * CAND + idx];
            int rw = g_cand_row[(size_t)q * CAND + idx];
            argv[s] = 127 - (int)(ck & 127u);
            key[s] = (ck & 0xffffffff00000000ull) | (u32)rw;
        }
    }

    for (int i = 0; i < KTOP; i++) {
        u64 m = 0;
        #pragma unroll
        for (int s = 0; s < 3; s++) m = key[s] > m ? key[s] : m;
        #pragma unroll
        for (int off = 16; off; off >>= 1) {
            u64 o = __shfl_xor_sync(0xffffffffu, m, off);
            if (o > m) m = o;
        }
        int have = 0;
        #pragma unroll
        for (int s = 2; s >= 0; s--) if (m && key[s] == m) have = s + 1;
        int myarg = have ? argv[have - 1] : 0;
        unsigned bal = __ballot_sync(0xffffffffu, have != 0);
        int srcl = __ffs(bal) - 1;
        int av = __shfl_sync(0xffffffffu, myarg, srcl);
        int hs = __shfl_sync(0xffffffffu, have, srcl);
        if (lane == srcl) key[hs - 1] = 0;
        int row = (int)(m & 0xffffffffull);
        float score = unokey((u32)(m >> 32));

        const float4* src = (const float4*)(T + ((size_t)row * NV + av) * ND);
        float4* dst = (float4*)(out + ((size_t)q * KTOP + i) * ND);
        dst[lane] = src[lane];
        if (lane == 0) {
            out[(size_t)NQ * KTOP * ND + (size_t)q * KTOP + i] = score;
            out[(size_t)NQ * KTOP * ND + (size_t)NQ * KTOP + (size_t)q * KTOP + i] =
                (float)(row * NV + av);
        }
    }
}

// ============================================================================
extern "C" void kernel_launch(void* const* d_in, const int* in_sizes, int n_in,
                              void* d_out, int out_size) {
    const float* Q = (const float*)d_in[0];
    const float* T = (const float*)d_in[1];
    if (n_in >= 2 && in_sizes[0] > in_sizes[1]) { const float* t = Q; Q = T; T = t; }

    cudaFuncSetAttribute(score_mma_kernel,
                         cudaFuncAttributeMaxDynamicSharedMemorySize, 98304);

    conv_T_kernel<<<(NR * NV * 4) / 256, 256>>>(T);   // init fused in
    conv_Q_kernel<<<(NQ * 4) / 256, 256>>>(Q);

    score_mma_kernel<<<dim3(32, 128), 512, 98304>>>();
    select_kernel<<<NQ, 256>>>();
    exact_kernel<<<NR, 256>>>(Q, T);
    final_kernel<<<(NQ * 32 + 255) / 256, 256>>>(T, (float*)d_out);
}

// round 16
// speedup vs baseline: 1.0537x; 1.0537x over previous
#include <cuda_runtime.h>
#include <cuda_fp16.h>
#include <cstdint>

typedef unsigned int u32;
typedef unsigned long long u64;

#define NQ   4096
#define NR   4096
#define NV   128
#define ND   128
#define KTOP 16
#define CAND 96
#define RCAP 768
#define CQ   16

// ---------------- device globals ----------------
__device__ u32 g_Tfp8[(size_t)NR * NV * ND / 4];   // 64 MB e4m3, fragment order
__device__ u32 g_Qfp8[(size_t)NQ * ND / 4];        // 512 KB, fragment order
__device__ u32 g_rowmax[(size_t)NQ * NR];          // okey(u32); RED.MAX target
__device__ int g_rowcnt[NR];
__device__ u32 g_rowlist[(size_t)NR * RCAP];       // (q<<7)|slot
__device__ int g_cand_row[(size_t)NQ * CAND];
__device__ u64 g_cand_key[(size_t)NQ * CAND];      // (okey(score)<<32)|(127-v)
__device__ int g_cand_cnt[NQ];

// ---------------- helpers ----------------
__device__ __forceinline__ u32 okey(float f) {
    u32 b = __float_as_uint(f);
    return (b & 0x80000000u) ? ~b : (b | 0x80000000u);
}
__device__ __forceinline__ float unokey(u32 u) {
    u32 b = (u & 0x80000000u) ? (u & 0x7fffffffu) : ~u;
    return __uint_as_float(b);
}
__device__ __forceinline__ float fmas(float a, float b, float c) {
    float d; asm("fma.rn.f32 %0, %1, %2, %3;" : "=f"(d) : "f"(a), "f"(b), "f"(c));
    return d;
}
__device__ __forceinline__ u32 pack_e4m3x4(float4 a) {
    unsigned short h0, h1; u32 r;
    asm("cvt.rn.satfinite.e4m3x2.f32 %0, %1, %2;" : "=h"(h0) : "f"(a.y), "f"(a.x));
    asm("cvt.rn.satfinite.e4m3x2.f32 %0, %1, %2;" : "=h"(h1) : "f"(a.w), "f"(a.z));
    asm("mov.b32 %0, {%1, %2};" : "=r"(r) : "h"(h0), "h"(h1));
    return r;
}
__device__ __forceinline__ u32 smem_u32(const void* p) {
    u32 a; asm("{ .reg .u64 t; cvta.to.shared.u64 t, %1; cvt.u32.u64 %0, t; }"
               : "=r"(a) : "l"(p));
    return a;
}
__device__ __forceinline__ void cpasync16(u32 saddr, const void* g) {
    asm volatile("cp.async.cg.shared.global [%0], [%1], 16;"
                 :: "r"(saddr), "l"(g) : "memory");
}
__device__ __forceinline__ u32 hmax2(u32 a, u32 b) {
    u32 d; asm("max.f16x2 %0, %1, %2;" : "=r"(d) : "r"(a), "r"(b)); return d;
}
__device__ __forceinline__ float hmax_to_f(u32 p) {
    __half2 h = *reinterpret_cast<__half2*>(&p);
    float2 f = __half22float2(h);
    return fmaxf(f.x, f.y);
}
#define CP_COMMIT() asm volatile("cp.async.commit_group;" ::: "memory")
#define CP_WAIT(n)  asm volatile("cp.async.wait_group %0;" :: "n"(n) : "memory")
#define BAR_GRP(id) asm volatile("bar.sync %0, 128;" :: "r"(id) : "memory")

// fp8 x fp8 -> fp16 accumulate (2x rate vs f32 acc); c = 2 x f16x2 regs
#define MMAFP8H(c, A, B0, B1) \
    asm volatile("mma.sync.aligned.m16n8k32.row.col.f16.e4m3.e4m3.f16 " \
        "{%0,%1}, {%2,%3,%4,%5}, {%6,%7}, {%0,%1};" \
        : "+r"((c)[0]), "+r"((c)[1]) \
        : "r"((A)[0]), "r"((A)[1]), "r"((A)[2]), "r"((A)[3]), "r"(B0), "r"(B1))

#define MMAFP8H_INIT(c, A, B0, B1) \
    asm volatile("mma.sync.aligned.m16n8k32.row.col.f16.e4m3.e4m3.f16 " \
        "{%0,%1}, {%2,%3,%4,%5}, {%6,%7}, {%8,%8};" \
        : "=r"((c)[0]), "=r"((c)[1]) \
        : "r"((A)[0]), "r"((A)[1]), "r"((A)[2]), "r"((A)[3]), "r"(B0), "r"(B1), \
          "r"(0u))

// ---------------- conversion (fragment-order layout) + fused init ----------
__global__ void conv_T_kernel(const float* __restrict__ T) {
    int t = blockIdx.x * 256 + threadIdx.x;
    if (t < NR) g_rowcnt[t] = 0;
    if (t < NQ * CAND) g_cand_key[t] = 0ull;
    int tg = t & 3, v = (t >> 2) & 127, r = t >> 9;
    const float* src = T + (size_t)r * 16384 + v * 128;
    u32 out[8];
    #pragma unroll
    for (int ks = 0; ks < 4; ks++)
        #pragma unroll
        for (int h = 0; h < 2; h++) {
            float4 f = *(const float4*)(src + ks * 32 + h * 16 + tg * 4);
            out[ks * 2 + h] = pack_e4m3x4(f);
        }
    uint4* dst = (uint4*)g_Tfp8 + (size_t)r * 1024 + v * 8 + tg * 2;
    dst[0] = make_uint4(out[0], out[1], out[2], out[3]);
    dst[1] = make_uint4(out[4], out[5], out[6], out[7]);
}
__global__ void conv_Q_kernel(const float* __restrict__ Q) {
    int t = blockIdx.x * 256 + threadIdx.x;
    int tg = t & 3, q = t >> 2;
    const float* src = Q + (size_t)q * 128;
    u32 out[8];
    #pragma unroll
    for (int ks = 0; ks < 4; ks++)
        #pragma unroll
        for (int h = 0; h < 2; h++) {
            float4 f = *(const float4*)(src + ks * 32 + h * 16 + tg * 4);
            out[ks * 2 + h] = pack_e4m3x4(f);
        }
    uint4* dst = (uint4*)g_Qfp8 + (size_t)q * 8 + tg * 2;
    dst[0] = make_uint4(out[0], out[1], out[2], out[3]);
    dst[1] = make_uint4(out[4], out[5], out[6], out[7]);
}

// ============================================================================
// Phase A: fp8 mma.sync scoring (fp16 accumulator), 4-warp-group decoupled.
// ROUND-14 VERBATIM (best measured: ~1362 us). Any added live register state
// regresses (R12, R15) — do not modify without a new operand plan.
// ============================================================================
__global__ void __launch_bounds__(512, 1)
score_mma_kernel() {
    __shared__ __align__(128) u32 pool[4 * 3 * 1024];   // 48 KB

    const int tid  = threadIdx.x;
    const int lane = tid & 31;
    const int wid  = tid >> 5;
    const int wm   = wid & 3;      // 32q slice; SMSP id
    const int wn   = wid >> 2;     // 32v quarter / group id
    const int g    = lane >> 2;
    const int tg   = lane & 3;
    const int qt   = blockIdx.x;   // 0..31 (fast -> L2 row sharing)
    const int rg   = blockIdx.y;   // 0..127

    u32* gbase = pool + wn * 3072;
    const u32 gbaddr = smem_u32(gbase);

    // ---- prologue: stage Q tile (16KB) into pool[0..4095], swizzled ----
    {
        const uint4* qsrc = (const uint4*)g_Qfp8 + (size_t)(qt * 128) * 8;
        #pragma unroll
        for (int i = 0; i < 2; i++) {
            int e = i * 512 + tid;
            int q = e >> 3, p = e & 7;
            *(uint4*)(pool + q * 32 + ((p ^ (q & 7)) << 2)) = qsrc[e];
        }
    }
    __syncthreads();

    // ---- hoist A fragments (full K, 2 q-tiles of 16) from swizzled Q ----
    u32 A[4][2][4];
    #pragma unroll
    for (int ks = 0; ks < 4; ks++)
        #pragma unroll
        for (int mt = 0; mt < 2; mt++) {
            int qlo = wm * 32 + mt * 16 + g;
            int j = tg * 8 + ks * 2;
            int c = j >> 2, w = j & 3;
            const u32* p0 = pool + qlo * 32 + ((c ^ g) << 2) + w;
            uint2 a02 = *(const uint2*)p0;
            uint2 a13 = *(const uint2*)(p0 + 256);
            A[ks][mt][0] = a02.x; A[ks][mt][2] = a02.y;
            A[ks][mt][1] = a13.x; A[ks][mt][3] = a13.y;
        }
    __syncthreads();

    // ---- staging map ----
    const int u = wm * 32 + lane;
    u32 soff[2];
    #pragma unroll
    for (int j4 = 0; j4 < 2; j4++) {
        int ck = j4 * 128 + u;
        int vl = ck >> 3, p = ck & 7;
        soff[j4] = (u32)(vl * 128 + ((p ^ (vl & 7)) * 16));
    }
    const uint4* tq = (const uint4*)g_Tfp8 + (size_t)(rg * 32) * 1024 + wn * 256;

    #pragma unroll
    for (int r0 = 0; r0 < 2; r0++) {
        const uint4* gsrc = tq + (size_t)r0 * 1024;
        #pragma unroll
        for (int j4 = 0; j4 < 2; j4++)
            cpasync16(gbaddr + r0 * 4096u + soff[j4], gsrc + j4 * 128 + u);
        CP_COMMIT();
    }
    CP_WAIT(1);

    u32 boff0[4], boff1[4];
    #pragma unroll
    for (int nt = 0; nt < 4; nt++) {
        int vl = nt * 8 + g;
        boff0[nt] = (u32)(vl * 32 + (((2 * tg) ^ g) << 2));
        boff1[nt] = (u32)(vl * 32 + (((2 * tg + 1) ^ g) << 2));
    }

    u32* rmbase = g_rowmax + (size_t)(qt * 128 + wm * 32 + g) * NR + rg * 32;
    const int barid = wn + 1;

    #pragma unroll 1
    for (int ri = 0; ri < 32; ri++) {
        BAR_GRP(barid);

        if (ri + 2 < 32) {
            const uint4* gsrc = tq + (size_t)(ri + 2) * 1024;
            u32 dst = gbaddr + (u32)((ri + 2) % 3) * 4096u;
            #pragma unroll
            for (int j4 = 0; j4 < 2; j4++)
                cpasync16(dst + soff[j4], gsrc + j4 * 128 + u);
            CP_COMMIT();
        }

        const u32* buf = gbase + (ri % 3) * 1024;
        u32 B[4][8];
        #pragma unroll
        for (int nt = 0; nt < 4; nt++) {
            uint4 b0 = *(const uint4*)(buf + boff0[nt]);
            uint4 b1 = *(const uint4*)(buf + boff1[nt]);
            B[nt][0] = b0.x; B[nt][1] = b0.y; B[nt][2] = b0.z; B[nt][3] = b0.w;
            B[nt][4] = b1.x; B[nt][5] = b1.y; B[nt][6] = b1.z; B[nt][7] = b1.w;
        }

        u32 acc[2][4][2];
        #pragma unroll
        for (int mt = 0; mt < 2; mt++)
            #pragma unroll
            for (int nt = 0; nt < 4; nt++)
                MMAFP8H_INIT(acc[mt][nt], A[0][mt], B[nt][0], B[nt][1]);
        #pragma unroll
        for (int ks = 1; ks < 4; ks++)
            #pragma unroll
            for (int mt = 0; mt < 2; mt++)
                #pragma unroll
                for (int nt = 0; nt < 4; nt++)
                    MMAFP8H(acc[mt][nt], A[ks][mt], B[nt][ks * 2], B[nt][ks * 2 + 1]);

        #pragma unroll
        for (int mt = 0; mt < 2; mt++) {
            u32 e0 = hmax2(hmax2(acc[mt][0][0], acc[mt][1][0]),
                           hmax2(acc[mt][2][0], acc[mt][3][0]));
            u32 e1 = hmax2(hmax2(acc[mt][0][1], acc[mt][1][1]),
                           hmax2(acc[mt][2][1], acc[mt][3][1]));
            e0 = hmax2(e0, __shfl_xor_sync(0xffffffffu, e0, 1));
            e0 = hmax2(e0, __shfl_xor_sync(0xffffffffu, e0, 2));
            e1 = hmax2(e1, __shfl_xor_sync(0xffffffffu, e1, 1));
            e1 = hmax2(e1, __shfl_xor_sync(0xffffffffu, e1, 2));
            if (tg == 0) {
                atomicMax(rmbase + (size_t)(mt * 16) * NR + ri, okey(hmax_to_f(e0)));
                atomicMax(rmbase + (size_t)(mt * 16 + 8) * NR + ri, okey(hmax_to_f(e1)));
            }
        }

        CP_WAIT(1);
    }
}

// ============================================================================
// Phase B: per-query candidate selection (rank-40 threshold, cap 96).
// ============================================================================
__global__ void select_kernel() {
    __shared__ u32 hist[256];
    __shared__ u32 s_b1, s_need, s_thr, s_cnt;
    const int tid = threadIdx.x;
    const int q = blockIdx.x;
    const uint4* sc4 = (const uint4*)(g_rowmax + (size_t)q * NR);

    hist[tid] = 0;
    __syncthreads();
    for (int j = tid; j < NR / 4; j += 256) {
        uint4 v = sc4[j];
        atomicAdd(&hist[v.x >> 24], 1u);
        atomicAdd(&hist[v.y >> 24], 1u);
        atomicAdd(&hist[v.z >> 24], 1u);
        atomicAdd(&hist[v.w >> 24], 1u);
    }
    __syncthreads();
    if (tid == 0) {
        u32 cum = 0;
        for (int b = 255; b >= 0; b--) {
            if (cum + hist[b] >= 40u) { s_b1 = (u32)b; s_need = 40u - cum; break; }
            cum += hist[b];
        }
    }
    __syncthreads();
    u32 b1 = s_b1, need = s_need;
    hist[tid] = 0;
    __syncthreads();
    for (int j = tid; j < NR / 4; j += 256) {
        uint4 v = sc4[j];
        if ((v.x >> 24) == b1) atomicAdd(&hist[(v.x >> 16) & 255u], 1u);
        if ((v.y >> 24) == b1) atomicAdd(&hist[(v.y >> 16) & 255u], 1u);
        if ((v.z >> 24) == b1) atomicAdd(&hist[(v.z >> 16) & 255u], 1u);
        if ((v.w >> 24) == b1) atomicAdd(&hist[(v.w >> 16) & 255u], 1u);
    }
    __syncthreads();
    if (tid == 0) {
        u32 cum = 0; u32 b2 = 0;
        for (int b = 255; b >= 0; b--) { cum += hist[b]; if (cum >= need) { b2 = (u32)b; break; } }
        s_thr = (b1 << 8) | b2;
        s_cnt = 0;
    }
    __syncthreads();
    u32 thr = s_thr;
    for (int j = tid; j < NR / 4; j += 256) {
        uint4 v = sc4[j];
        u32 e[4] = {v.x, v.y, v.z, v.w};
        #pragma unroll
        for (int c = 0; c < 4; c++) {
            if ((e[c] >> 16) >= thr) {
                int jj = j * 4 + c;
                u32 pos = atomicAdd(&s_cnt, 1u);
                if (pos < CAND) {
                    g_cand_row[(size_t)q * CAND + pos] = jj;
                    int p2 = atomicAdd(&g_rowcnt[jj], 1);
                    if (p2 < RCAP) g_rowlist[(size_t)jj * RCAP + p2] = ((u32)q << 7) | pos;
                }
            }
        }
    }
    __syncthreads();
    if (tid == 0) g_cand_cnt[q] = (int)(s_cnt < CAND ? s_cnt : CAND);
}

// ============================================================================
// Phase C: exact recompute, bitwise-matching reference (in-order fp32 FMA
// chain over k=0..127, single accumulator). CTA = (row, half): halves of a
// row run on different SMs; merge via atomicMax on g_cand_key (idempotent).
// ============================================================================
__global__ void __launch_bounds__(256)
exact_kernel(const float* __restrict__ Q, const float* __restrict__ T) {
    __shared__ __align__(16) float Ts[64 * 132];
    __shared__ __align__(16) float Qs[CQ * 128];
    __shared__ u64 sres[CQ];
    __shared__ u32 sent[CQ];

    const int tid = threadIdx.x;
    const int r = blockIdx.x >> 1;
    const int h = blockIdx.x & 1;
    int nq = g_rowcnt[r];
    if (nq > RCAP) nq = RCAP;
    if (nq == 0) return;
    const int g = tid >> 6;
    const int v = tid & 63;

    // stage this half's 64 vectors
    {
        const float4* src = (const float4*)(T + (size_t)r * NV * ND
                                            + (size_t)h * 64 * ND);
        #pragma unroll
        for (int i = 0; i < 8; i++) {
            int e = i * 256 + tid;
            int vv = e >> 5, k4 = e & 31;
            *(float4*)(Ts + vv * 132 + k4 * 4) = src[e];
        }
    }

    #pragma unroll 1
    for (int s = 0; s < nq; s += CQ) {
        int cnt = nq - s; if (cnt > CQ) cnt = CQ;
        __syncthreads();   // Ts visible (first iter) / prev sweep fully done
        if (tid < CQ) {
            sres[tid] = 0ull;
            sent[tid] = (tid < cnt) ? g_rowlist[(size_t)r * RCAP + s + tid] : 0u;
        }
        __syncthreads();
        #pragma unroll
        for (int i = 0; i < 2; i++) {
            int e = i * 256 + tid;
            int qq = e >> 5, k4 = e & 31;
            if (qq < cnt) {
                int qidx = (int)(sent[qq] >> 7);
                *(float4*)(Qs + qq * 128 + k4 * 4) =
                    ((const float4*)(Q + (size_t)qidx * ND))[k4];
            }
        }
        __syncthreads();

        float a0 = 0.f, a1 = 0.f, a2 = 0.f, a3 = 0.f;
        const float* tv = Ts + v * 132;
        const float* q0 = Qs + (g * 4 + 0) * 128;
        const float* q1 = Qs + (g * 4 + 1) * 128;
        const float* q2 = Qs + (g * 4 + 2) * 128;
        const float* q3 = Qs + (g * 4 + 3) * 128;
        #pragma unroll 8
        for (int k = 0; k < 128; k += 4) {
            float4 t4 = *(const float4*)(tv + k);
            float4 x0 = *(const float4*)(q0 + k);
            float4 x1 = *(const float4*)(q1 + k);
            float4 x2 = *(const float4*)(q2 + k);
            float4 x3 = *(const float4*)(q3 + k);
            a0 = fmas(x0.x, t4.x, a0); a0 = fmas(x0.y, t4.y, a0);
            a0 = fmas(x0.z, t4.z, a0); a0 = fmas(x0.w, t4.w, a0);
            a1 = fmas(x1.x, t4.x, a1); a1 = fmas(x1.y, t4.y, a1);
            a1 = fmas(x1.z, t4.z, a1); a1 = fmas(x1.w, t4.w, a1);
            a2 = fmas(x2.x, t4.x, a2); a2 = fmas(x2.y, t4.y, a2);
            a2 = fmas(x2.z, t4.z, a2); a2 = fmas(x2.w, t4.w, a2);
            a3 = fmas(x3.x, t4.x, a3); a3 = fmas(x3.y, t4.y, a3);
            a3 = fmas(x3.z, t4.z, a3); a3 = fmas(x3.w, t4.w, a3);
        }
        u64 vb = (u64)(u32)(127 - (h * 64 + v));
        atomicMax(&sres[g * 4 + 0], ((u64)okey(a0) << 32) | vb);
        atomicMax(&sres[g * 4 + 1], ((u64)okey(a1) << 32) | vb);
        atomicMax(&sres[g * 4 + 2], ((u64)okey(a2) << 32) | vb);
        atomicMax(&sres[g * 4 + 3], ((u64)okey(a3) << 32) | vb);
        __syncthreads();
        if (tid < cnt) {
            u32 ent = sent[tid];
            int q = (int)(ent >> 7), slot = (int)(ent & 127u);
            atomicMax(&g_cand_key[(size_t)q * CAND + slot], sres[tid]);
        }
    }
}

// ============================================================================
// Phase D: exact top-16 among <=96 candidates + gather (score desc, row desc).
// Output: [values 4096*16*128 | scores 4096*16 | ids 4096*16] (f32).
// ============================================================================
__global__ void final_kernel(const float* __restrict__ T, float* __restrict__ out) {
    int gw = (blockIdx.x * blockDim.x + threadIdx.x) >> 5;
    int lane = threadIdx.x & 31;
    if (gw >= NQ) return;
    const int q = gw;
    int cnt = g_cand_cnt[q];

    u64 key[3]; int argv[3];
    #pragma unroll
    for (int s = 0; s < 3; s++) {
        int idx = lane + 32 * s;
        key[s] = 0; argv[s] = 0;
        if (idx < cnt) {
            u64 ck = g_cand_key[(size_t)q * CAND + idx];
            int rw = g_cand_row[(size_t)q * CAND + idx];
            argv[s] = 127 - (int)(ck & 127u);
            key[s] = (ck & 0xffffffff00000000ull) | (u32)rw;
        }
    }

    for (int i = 0; i < KTOP; i++) {
        u64 m = 0;
        #pragma unroll
        for (int s = 0; s < 3; s++) m = key[s] > m ? key[s] : m;
        #pragma unroll
        for (int off = 16; off; off >>= 1) {
            u64 o = __shfl_xor_sync(0xffffffffu, m, off);
            if (o > m) m = o;
        }
        int have = 0;
        #pragma unroll
        for (int s = 2; s >= 0; s--) if (m && key[s] == m) have = s + 1;
        int myarg = have ? argv[have - 1] : 0;
        unsigned bal = __ballot_sync(0xffffffffu, have != 0);
        int srcl = __ffs(bal) - 1;
        int av = __shfl_sync(0xffffffffu, myarg, srcl);
        int hs = __shfl_sync(0xffffffffu, have, srcl);
        if (lane == srcl) key[hs - 1] = 0;
        int row = (int)(m & 0xffffffffull);
        float score = unokey((u32)(m >> 32));

        const float4* src = (const float4*)(T + ((size_t)row * NV + av) * ND);
        float4* dst = (float4*)(out + ((size_t)q * KTOP + i) * ND);
        dst[lane] = src[lane];
        if (lane == 0) {
            out[(size_t)NQ * KTOP * ND + (size_t)q * KTOP + i] = score;
            out[(size_t)NQ * KTOP * ND + (size_t)NQ * KTOP + (size_t)q * KTOP + i] =
                (float)(row * NV + av);
        }
    }
}

// ============================================================================
extern "C" void kernel_launch(void* const* d_in, const int* in_sizes, int n_in,
                              void* d_out, int out_size) {
    const float* Q = (const float*)d_in[0];
    const float* T = (const float*)d_in[1];
    if (n_in >= 2 && in_sizes[0] > in_sizes[1]) { const float* t = Q; Q = T; T = t; }

    conv_T_kernel<<<(NR * NV * 4) / 256, 256>>>(T);   // init fused in
    conv_Q_kernel<<<(NQ * 4) / 256, 256>>>(Q);

    score_mma_kernel<<<dim3(32, 128), 512>>>();
    select_kernel<<<NQ, 256>>>();
    exact_kernel<<<NR * 2, 256>>>(Q, T);
    final_kernel<<<(NQ * 32 + 255) / 256, 256>>>(T, (float*)d_out);
}

// round 17
// speedup vs baseline: 1.0888x; 1.0333x over previous
#include <cuda_runtime.h>
#include <cuda_fp16.h>
#include <cstdint>

typedef unsigned int u32;
typedef unsigned long long u64;

#define NQ   4096
#define NR   4096
#define NV   128
#define ND   128
#define KTOP 16
#define CAND 96
#define RCAP 768
#define CQ   16

// ---------------- device globals ----------------
__device__ u32 g_Tfp8[(size_t)NR * NV * ND / 4];   // 64 MB e4m3, fragment order
__device__ u32 g_Qfp8[(size_t)NQ * ND / 4];        // 512 KB, fragment order
__device__ u32 g_rowmax[(size_t)NQ * NR];          // okey(u32); RED.MAX target
__device__ int g_rowcnt[NR];
__device__ u32 g_rowlist[(size_t)NR * RCAP];       // (q<<7)|slot
__device__ int g_cand_row[(size_t)NQ * CAND];
__device__ u64 g_cand_key[(size_t)NQ * CAND];      // (okey(score)<<32)|(127-v)
__device__ int g_cand_cnt[NQ];

// ---------------- helpers ----------------
__device__ __forceinline__ u32 okey(float f) {
    u32 b = __float_as_uint(f);
    return (b & 0x80000000u) ? ~b : (b | 0x80000000u);
}
__device__ __forceinline__ float unokey(u32 u) {
    u32 b = (u & 0x80000000u) ? (u & 0x7fffffffu) : ~u;
    return __uint_as_float(b);
}
__device__ __forceinline__ float fmas(float a, float b, float c) {
    float d; asm("fma.rn.f32 %0, %1, %2, %3;" : "=f"(d) : "f"(a), "f"(b), "f"(c));
    return d;
}
__device__ __forceinline__ u32 pack_e4m3x4(float4 a) {
    unsigned short h0, h1; u32 r;
    asm("cvt.rn.satfinite.e4m3x2.f32 %0, %1, %2;" : "=h"(h0) : "f"(a.y), "f"(a.x));
    asm("cvt.rn.satfinite.e4m3x2.f32 %0, %1, %2;" : "=h"(h1) : "f"(a.w), "f"(a.z));
    asm("mov.b32 %0, {%1, %2};" : "=r"(r) : "h"(h0), "h"(h1));
    return r;
}
__device__ __forceinline__ u32 smem_u32(const void* p) {
    u32 a; asm("{ .reg .u64 t; cvta.to.shared.u64 t, %1; cvt.u32.u64 %0, t; }"
               : "=r"(a) : "l"(p));
    return a;
}
__device__ __forceinline__ void cpasync16(u32 saddr, const void* g) {
    asm volatile("cp.async.cg.shared.global [%0], [%1], 16;"
                 :: "r"(saddr), "l"(g) : "memory");
}
__device__ __forceinline__ u32 hmax2(u32 a, u32 b) {
    u32 d; asm("max.f16x2 %0, %1, %2;" : "=r"(d) : "r"(a), "r"(b)); return d;
}
__device__ __forceinline__ float hmax_to_f(u32 p) {
    __half2 h = *reinterpret_cast<__half2*>(&p);
    float2 f = __half22float2(h);
    return fmaxf(f.x, f.y);
}
#define CP_COMMIT() asm volatile("cp.async.commit_group;" ::: "memory")
#define CP_WAIT(n)  asm volatile("cp.async.wait_group %0;" :: "n"(n) : "memory")
#define BAR_GRP(id) asm volatile("bar.sync %0, 128;" :: "r"(id) : "memory")

// fp8 x fp8 -> fp16 accumulate (2x rate vs f32 acc); c = 2 x f16x2 regs
#define MMAFP8H(c, A, B0, B1) \
    asm volatile("mma.sync.aligned.m16n8k32.row.col.f16.e4m3.e4m3.f16 " \
        "{%0,%1}, {%2,%3,%4,%5}, {%6,%7}, {%0,%1};" \
        : "+r"((c)[0]), "+r"((c)[1]) \
        : "r"((A)[0]), "r"((A)[1]), "r"((A)[2]), "r"((A)[3]), "r"(B0), "r"(B1))

#define MMAFP8H_INIT(c, A, B0, B1) \
    asm volatile("mma.sync.aligned.m16n8k32.row.col.f16.e4m3.e4m3.f16 " \
        "{%0,%1}, {%2,%3,%4,%5}, {%6,%7}, {%8,%8};" \
        : "=r"((c)[0]), "=r"((c)[1]) \
        : "r"((A)[0]), "r"((A)[1]), "r"((A)[2]), "r"((A)[3]), "r"(B0), "r"(B1), \
          "r"(0u))

// ---------------- conversion (fragment-order layout) + fused init ----------
__global__ void conv_T_kernel(const float* __restrict__ T) {
    int t = blockIdx.x * 256 + threadIdx.x;
    if (t < NR) g_rowcnt[t] = 0;
    if (t < NQ * CAND) g_cand_key[t] = 0ull;
    int tg = t & 3, v = (t >> 2) & 127, r = t >> 9;
    const float* src = T + (size_t)r * 16384 + v * 128;
    u32 out[8];
    #pragma unroll
    for (int ks = 0; ks < 4; ks++)
        #pragma unroll
        for (int h = 0; h < 2; h++) {
            float4 f = *(const float4*)(src + ks * 32 + h * 16 + tg * 4);
            out[ks * 2 + h] = pack_e4m3x4(f);
        }
    uint4* dst = (uint4*)g_Tfp8 + (size_t)r * 1024 + v * 8 + tg * 2;
    dst[0] = make_uint4(out[0], out[1], out[2], out[3]);
    dst[1] = make_uint4(out[4], out[5], out[6], out[7]);
}
__global__ void conv_Q_kernel(const float* __restrict__ Q) {
    int t = blockIdx.x * 256 + threadIdx.x;
    int tg = t & 3, q = t >> 2;
    const float* src = Q + (size_t)q * 128;
    u32 out[8];
    #pragma unroll
    for (int ks = 0; ks < 4; ks++)
        #pragma unroll
        for (int h = 0; h < 2; h++) {
            float4 f = *(const float4*)(src + ks * 32 + h * 16 + tg * 4);
            out[ks * 2 + h] = pack_e4m3x4(f);
        }
    uint4* dst = (uint4*)g_Qfp8 + (size_t)q * 8 + tg * 2;
    dst[0] = make_uint4(out[0], out[1], out[2], out[3]);
    dst[1] = make_uint4(out[4], out[5], out[6], out[7]);
}

// ============================================================================
// Phase A: fp8 mma.sync (fp16 acc), 4-warp-group decoupled, ROW PAIRS with
// strictly sequential row processing (one B set + one acc set live at a
// time — the R15 lesson). 6-stage 24KB ring per group (96KB dynamic smem),
// staged 4 rows ahead; one BAR_GRP + one CP_WAIT per 2 rows.
// ============================================================================
__global__ void __launch_bounds__(512, 1)
score_mma_kernel() {
    extern __shared__ __align__(128) u32 dynpool[];   // 96 KB

    const int tid  = threadIdx.x;
    const int lane = tid & 31;
    const int wid  = tid >> 5;
    const int wm   = wid & 3;      // 32q slice; SMSP id
    const int wn   = wid >> 2;     // 32v quarter / group id
    const int g    = lane >> 2;
    const int tg   = lane & 3;
    const int qt   = blockIdx.x;   // 0..31 (fast -> L2 row sharing)
    const int rg   = blockIdx.y;   // 0..127

    u32* gbase = dynpool + wn * 6144;          // 6 stages x 1024 u32
    const u32 gbaddr = smem_u32(gbase);

    // ---- prologue: stage Q tile (16KB) into dynpool[0..4095], swizzled ----
    {
        const uint4* qsrc = (const uint4*)g_Qfp8 + (size_t)(qt * 128) * 8;
        #pragma unroll
        for (int i = 0; i < 2; i++) {
            int e = i * 512 + tid;
            int q = e >> 3, p = e & 7;
            *(uint4*)(dynpool + q * 32 + ((p ^ (q & 7)) << 2)) = qsrc[e];
        }
    }
    __syncthreads();

    // ---- hoist A fragments (full K, 2 q-tiles of 16) from swizzled Q ----
    u32 A[4][2][4];
    #pragma unroll
    for (int ks = 0; ks < 4; ks++)
        #pragma unroll
        for (int mt = 0; mt < 2; mt++) {
            int qlo = wm * 32 + mt * 16 + g;
            int j = tg * 8 + ks * 2;
            int c = j >> 2, w = j & 3;
            const u32* p0 = dynpool + qlo * 32 + ((c ^ g) << 2) + w;
            uint2 a02 = *(const uint2*)p0;
            uint2 a13 = *(const uint2*)(p0 + 256);
            A[ks][mt][0] = a02.x; A[ks][mt][2] = a02.y;
            A[ks][mt][1] = a13.x; A[ks][mt][3] = a13.y;
        }
    __syncthreads();   // all hoists done before cp.async overwrites pool

    // ---- staging map: group's 128 threads stage a 4KB quarter per row ----
    const int u = wm * 32 + lane;
    u32 soff[2];
    #pragma unroll
    for (int j4 = 0; j4 < 2; j4++) {
        int ck = j4 * 128 + u;
        int vl = ck >> 3, p = ck & 7;
        soff[j4] = (u32)(vl * 128 + ((p ^ (vl & 7)) * 16));
    }
    const uint4* tq = (const uint4*)g_Tfp8 + (size_t)(rg * 32) * 1024 + wn * 256;

    // prologue: stage rows 0..3 into slots 0..3 (one commit per row)
    #pragma unroll
    for (int r0 = 0; r0 < 4; r0++) {
        const uint4* gsrc = tq + (size_t)r0 * 1024;
        u32 dst = gbaddr + (u32)r0 * 4096u;
        #pragma unroll
        for (int j4 = 0; j4 < 2; j4++)
            cpasync16(dst + soff[j4], gsrc + j4 * 128 + u);
        CP_COMMIT();
    }
    CP_WAIT(2);   // rows 0,1 complete (own copies); group bar publishes

    u32 boff0[4], boff1[4];
    #pragma unroll
    for (int nt = 0; nt < 4; nt++) {
        int vl = nt * 8 + g;
        boff0[nt] = (u32)(vl * 32 + (((2 * tg) ^ g) << 2));
        boff1[nt] = (u32)(vl * 32 + (((2 * tg + 1) ^ g) << 2));
    }

    u32* rmbase = g_rowmax + (size_t)(qt * 128 + wm * 32 + g) * NR + rg * 32;
    const int barid = wn + 1;

    int s0 = 0;   // slot of pair's first row; rotates 0 -> 2 -> 4 -> 0
    #pragma unroll 1
    for (int pi = 0; pi < 16; pi++) {
        BAR_GRP(barid);   // rows 2pi,2pi+1 published; pair pi-1 reads done

        // stage rows 2pi+4, 2pi+5 into slots s0+4, s0+5 (mod 6) —
        // those slots held rows 2pi-2, 2pi-1, read in pair pi-1.
        if (pi + 2 < 16) {
            int st = s0 + 4; if (st >= 6) st -= 6;
            #pragma unroll
            for (int rr = 0; rr < 2; rr++) {
                const uint4* gsrc = tq + (size_t)(2 * (pi + 2) + rr) * 1024;
                u32 dst = gbaddr + (u32)(st + rr) * 4096u;
                #pragma unroll
                for (int j4 = 0; j4 < 2; j4++)
                    cpasync16(dst + soff[j4], gsrc + j4 * 128 + u);
                CP_COMMIT();
            }
        }

        // ---- two rows, strictly sequential (one B + one acc live) ----
        #pragma unroll
        for (int rr = 0; rr < 2; rr++) {
            const u32* buf = gbase + (s0 + rr) * 1024;
            u32 B[4][8];
            #pragma unroll
            for (int nt = 0; nt < 4; nt++) {
                uint4 b0 = *(const uint4*)(buf + boff0[nt]);
                uint4 b1 = *(const uint4*)(buf + boff1[nt]);
                B[nt][0] = b0.x; B[nt][1] = b0.y; B[nt][2] = b0.z; B[nt][3] = b0.w;
                B[nt][4] = b1.x; B[nt][5] = b1.y; B[nt][6] = b1.z; B[nt][7] = b1.w;
            }

            u32 acc[2][4][2];
            #pragma unroll
            for (int mt = 0; mt < 2; mt++)
                #pragma unroll
                for (int nt = 0; nt < 4; nt++)
                    MMAFP8H_INIT(acc[mt][nt], A[0][mt], B[nt][0], B[nt][1]);
            #pragma unroll
            for (int ks = 1; ks < 4; ks++)
                #pragma unroll
                for (int mt = 0; mt < 2; mt++)
                    #pragma unroll
                    for (int nt = 0; nt < 4; nt++)
                        MMAFP8H(acc[mt][nt], A[ks][mt], B[nt][ks * 2], B[nt][ks * 2 + 1]);

            #pragma unroll
            for (int mt = 0; mt < 2; mt++) {
                u32 e0 = hmax2(hmax2(acc[mt][0][0], acc[mt][1][0]),
                               hmax2(acc[mt][2][0], acc[mt][3][0]));
                u32 e1 = hmax2(hmax2(acc[mt][0][1], acc[mt][1][1]),
                               hmax2(acc[mt][2][1], acc[mt][3][1]));
                e0 = hmax2(e0, __shfl_xor_sync(0xffffffffu, e0, 1));
                e0 = hmax2(e0, __shfl_xor_sync(0xffffffffu, e0, 2));
                e1 = hmax2(e1, __shfl_xor_sync(0xffffffffu, e1, 1));
                e1 = hmax2(e1, __shfl_xor_sync(0xffffffffu, e1, 2));
                if (tg == 0) {
                    int row = 2 * pi + rr;
                    atomicMax(rmbase + (size_t)(mt * 16) * NR + row, okey(hmax_to_f(e0)));
                    atomicMax(rmbase + (size_t)(mt * 16 + 8) * NR + row, okey(hmax_to_f(e1)));
                }
            }
        }

        CP_WAIT(2);   // rows 2pi+2,2pi+3 complete (own); next bar publishes
        s0 += 2; if (s0 >= 6) s0 = 0;
    }
}

// ============================================================================
// Phase B: per-query candidate selection (rank-40 threshold, cap 96).
// ============================================================================
__global__ void select_kernel() {
    __shared__ u32 hist[256];
    __shared__ u32 s_b1, s_need, s_thr, s_cnt;
    const int tid = threadIdx.x;
    const int q = blockIdx.x;
    const uint4* sc4 = (const uint4*)(g_rowmax + (size_t)q * NR);

    hist[tid] = 0;
    __syncthreads();
    for (int j = tid; j < NR / 4; j += 256) {
        uint4 v = sc4[j];
        atomicAdd(&hist[v.x >> 24], 1u);
        atomicAdd(&hist[v.y >> 24], 1u);
        atomicAdd(&hist[v.z >> 24], 1u);
        atomicAdd(&hist[v.w >> 24], 1u);
    }
    __syncthreads();
    if (tid == 0) {
        u32 cum = 0;
        for (int b = 255; b >= 0; b--) {
            if (cum + hist[b] >= 40u) { s_b1 = (u32)b; s_need = 40u - cum; break; }
            cum += hist[b];
        }
    }
    __syncthreads();
    u32 b1 = s_b1, need = s_need;
    hist[tid] = 0;
    __syncthreads();
    for (int j = tid; j < NR / 4; j += 256) {
        uint4 v = sc4[j];
        if ((v.x >> 24) == b1) atomicAdd(&hist[(v.x >> 16) & 255u], 1u);
        if ((v.y >> 24) == b1) atomicAdd(&hist[(v.y >> 16) & 255u], 1u);
        if ((v.z >> 24) == b1) atomicAdd(&hist[(v.z >> 16) & 255u], 1u);
        if ((v.w >> 24) == b1) atomicAdd(&hist[(v.w >> 16) & 255u], 1u);
    }
    __syncthreads();
    if (tid == 0) {
        u32 cum = 0; u32 b2 = 0;
        for (int b = 255; b >= 0; b--) { cum += hist[b]; if (cum >= need) { b2 = (u32)b; break; } }
        s_thr = (b1 << 8) | b2;
        s_cnt = 0;
    }
    __syncthreads();
    u32 thr = s_thr;
    for (int j = tid; j < NR / 4; j += 256) {
        uint4 v = sc4[j];
        u32 e[4] = {v.x, v.y, v.z, v.w};
        #pragma unroll
        for (int c = 0; c < 4; c++) {
            if ((e[c] >> 16) >= thr) {
                int jj = j * 4 + c;
                u32 pos = atomicAdd(&s_cnt, 1u);
                if (pos < CAND) {
                    g_cand_row[(size_t)q * CAND + pos] = jj;
                    int p2 = atomicAdd(&g_rowcnt[jj], 1);
                    if (p2 < RCAP) g_rowlist[(size_t)jj * RCAP + p2] = ((u32)q << 7) | pos;
                }
            }
        }
    }
    __syncthreads();
    if (tid == 0) g_cand_cnt[q] = (int)(s_cnt < CAND ? s_cnt : CAND);
}

// ============================================================================
// Phase C: exact recompute, bitwise-matching reference (in-order fp32 FMA
// chain over k=0..127, single accumulator). CTA = (row, half).
// ============================================================================
__global__ void __launch_bounds__(256)
exact_kernel(const float* __restrict__ Q, const float* __restrict__ T) {
    __shared__ __align__(16) float Ts[64 * 132];
    __shared__ __align__(16) float Qs[CQ * 128];
    __shared__ u64 sres[CQ];
    __shared__ u32 sent[CQ];

    const int tid = threadIdx.x;
    const int r = blockIdx.x >> 1;
    const int h = blockIdx.x & 1;
    int nq = g_rowcnt[r];
    if (nq > RCAP) nq = RCAP;
    if (nq == 0) return;
    const int g = tid >> 6;
    const int v = tid & 63;

    {
        const float4* src = (const float4*)(T + (size_t)r * NV * ND
                                            + (size_t)h * 64 * ND);
        #pragma unroll
        for (int i = 0; i < 8; i++) {
            int e = i * 256 + tid;
            int vv = e >> 5, k4 = e & 31;
            *(float4*)(Ts + vv * 132 + k4 * 4) = src[e];
        }
    }

    #pragma unroll 1
    for (int s = 0; s < nq; s += CQ) {
        int cnt = nq - s; if (cnt > CQ) cnt = CQ;
        __syncthreads();
        if (tid < CQ) {
            sres[tid] = 0ull;
            sent[tid] = (tid < cnt) ? g_rowlist[(size_t)r * RCAP + s + tid] : 0u;
        }
        __syncthreads();
        #pragma unroll
        for (int i = 0; i < 2; i++) {
            int e = i * 256 + tid;
            int qq = e >> 5, k4 = e & 31;
            if (qq < cnt) {
                int qidx = (int)(sent[qq] >> 7);
                *(float4*)(Qs + qq * 128 + k4 * 4) =
                    ((const float4*)(Q + (size_t)qidx * ND))[k4];
            }
        }
        __syncthreads();

        float a0 = 0.f, a1 = 0.f, a2 = 0.f, a3 = 0.f;
        const float* tv = Ts + v * 132;
        const float* q0 = Qs + (g * 4 + 0) * 128;
        const float* q1 = Qs + (g * 4 + 1) * 128;
        const float* q2 = Qs + (g * 4 + 2) * 128;
        const float* q3 = Qs + (g * 4 + 3) * 128;
        #pragma unroll 8
        for (int k = 0; k < 128; k += 4) {
            float4 t4 = *(const float4*)(tv + k);
            float4 x0 = *(const float4*)(q0 + k);
            float4 x1 = *(const float4*)(q1 + k);
            float4 x2 = *(const float4*)(q2 + k);
            float4 x3 = *(const float4*)(q3 + k);
            a0 = fmas(x0.x, t4.x, a0); a0 = fmas(x0.y, t4.y, a0);
            a0 = fmas(x0.z, t4.z, a0); a0 = fmas(x0.w, t4.w, a0);
            a1 = fmas(x1.x, t4.x, a1); a1 = fmas(x1.y, t4.y, a1);
            a1 = fmas(x1.z, t4.z, a1); a1 = fmas(x1.w, t4.w, a1);
            a2 = fmas(x2.x, t4.x, a2); a2 = fmas(x2.y, t4.y, a2);
            a2 = fmas(x2.z, t4.z, a2); a2 = fmas(x2.w, t4.w, a2);
            a3 = fmas(x3.x, t4.x, a3); a3 = fmas(x3.y, t4.y, a3);
            a3 = fmas(x3.z, t4.z, a3); a3 = fmas(x3.w, t4.w, a3);
        }
        u64 vb = (u64)(u32)(127 - (h * 64 + v));
        atomicMax(&sres[g * 4 + 0], ((u64)okey(a0) << 32) | vb);
        atomicMax(&sres[g * 4 + 1], ((u64)okey(a1) << 32) | vb);
        atomicMax(&sres[g * 4 + 2], ((u64)okey(a2) << 32) | vb);
        atomicMax(&sres[g * 4 + 3], ((u64)okey(a3) << 32) | vb);
        __syncthreads();
        if (tid < cnt) {
            u32 ent = sent[tid];
            int q = (int)(ent >> 7), slot = (int)(ent & 127u);
            atomicMax(&g_cand_key[(size_t)q * CAND + slot], sres[tid]);
        }
    }
}

// ============================================================================
// Phase D: exact top-16 among <=96 candidates + gather (score desc, row desc).
// Output: [values 4096*16*128 | scores 4096*16 | ids 4096*16] (f32).
// ============================================================================
__global__ void final_kernel(const float* __restrict__ T, float* __restrict__ out) {
    int gw = (blockIdx.x * blockDim.x + threadIdx.x) >> 5;
    int lane = threadIdx.x & 31;
    if (gw >= NQ) return;
    const int q = gw;
    int cnt = g_cand_cnt[q];

    u64 key[3]; int argv[3];
    #pragma unroll
    for (int s = 0; s < 3; s++) {
        int idx = lane + 32 * s;
        key[s] = 0; argv[s] = 0;
        if (idx < cnt) {
            u64 ck = g_cand_key[(size_t)q * CAND + idx];
            int rw = g_cand_row[(size_t)q * CAND + idx];
            argv[s] = 127 - (int)(ck & 127u);
            key[s] = (ck & 0xffffffff00000000ull) | (u32)rw;
        }
    }

    for (int i = 0; i < KTOP; i++) {
        u64 m = 0;
        #pragma unroll
        for (int s = 0; s < 3; s++) m = key[s] > m ? key[s] : m;
        #pragma unroll
        for (int off = 16; off; off >>= 1) {
            u64 o = __shfl_xor_sync(0xffffffffu, m, off);
            if (o > m) m = o;
        }
        int have = 0;
        #pragma unroll
        for (int s = 2; s >= 0; s--) if (m && key[s] == m) have = s + 1;
        int myarg = have ? argv[have - 1] : 0;
        unsigned bal = __ballot_sync(0xffffffffu, have != 0);
        int srcl = __ffs(bal) - 1;
        int av = __shfl_sync(0xffffffffu, myarg, srcl);
        int hs = __shfl_sync(0xffffffffu, have, srcl);
        if (lane == srcl) key[hs - 1] = 0;
        int row = (int)(m & 0xffffffffull);
        float score = unokey((u32)(m >> 32));

        const float4* src = (const float4*)(T + ((size_t)row * NV + av) * ND);
        float4* dst = (float4*)(out + ((size_t)q * KTOP + i) * ND);
        dst[lane] = src[lane];
        if (lane == 0) {
            out[(size_t)NQ * KTOP * ND + (size_t)q * KTOP + i] = score;
            out[(size_t)NQ * KTOP * ND + (size_t)NQ * KTOP + (size_t)q * KTOP + i] =
                (float)(row * NV + av);
        }
    }
}

// ============================================================================
extern "C" void kernel_launch(void* const* d_in, const int* in_sizes, int n_in,
                              void* d_out, int out_size) {
    const float* Q = (const float*)d_in[0];
    const float* T = (const float*)d_in[1];
    if (n_in >= 2 && in_sizes[0] > in_sizes[1]) { const float* t = Q; Q = T; T = t; }

    cudaFuncSetAttribute(score_mma_kernel,
                         cudaFuncAttributeMaxDynamicSharedMemorySize, 98304);

    conv_T_kernel<<<(NR * NV * 4) / 256, 256>>>(T);   // init fused in
    conv_Q_kernel<<<(NQ * 4) / 256, 256>>>(Q);

    score_mma_kernel<<<dim3(32, 128), 512, 98304>>>();
    select_kernel<<<NQ, 256>>>();
    exact_kernel<<<NR * 2, 256>>>(Q, T);
    final_kernel<<<(NQ * 32 + 255) / 256, 256>>>(T, (float*)d_out);
}